// round 15
// baseline (speedup 1.0000x reference)
#include <cuda_runtime.h>
#include <cuda_fp16.h>
#include <cstddef>
#include <cstdint>

#define TOK_N 8192
#define KK    4
#define BB    16
#define MM    64
#define DD    512
#define DP1   513
#define NPAIR (TOK_N*KK)   // 32768
#define SLAB  1024
#define NT1   9            // phase1 tiles per expert
#define BATCH 32           // pairs per phase1 batch
#define NT2   8            // phase2 tiles per expert (R10-proven)
#define PPW   4            // phase2 pairs per warp per sweep (R10-proven)

// packed f32x2 helpers (sm_103a; FFMA2 only reachable via PTX)
#define FMA2(acc, a, b) \
    asm("fma.rn.f32x2 %0, %1, %2, %0;" : "+l"(acc) : "l"(a), "l"(b))
#define PACK2(dst, f) \
    asm("mov.b64 %0, {%1, %1};" : "=l"(dst) : "f"(f))
#define UNPACK2(lo, hi, v) \
    asm("mov.b64 {%0, %1}, %2;" : "=f"(lo), "=f"(hi) : "l"(v))

// ---- scratch ----
__device__ float  g_inv[MM * BB];
__device__ int    g_cnt[MM];
__device__ int    g_list[MM * SLAB];
__device__ __half g_wph[(size_t)NPAIR * DD];   // 32 MB fp16 partials
__device__ float  g_partial[MM * NT2];

// ---------------------------------------------------------------------------
// K1: column norms. inv[m,b] = rsqrt( sum_{d=0..512} U[m,d,b]^2 )
// ---------------------------------------------------------------------------
__global__ void __launch_bounds__(256) norm_kernel(const float* __restrict__ U) {
    __shared__ float s[256 * 4];
    const int e = blockIdx.x, t = threadIdx.x;
    const float4* Ue = reinterpret_cast<const float4*>(U + (size_t)e * DP1 * BB);
    float a0 = 0.f, a1 = 0.f, a2 = 0.f, a3 = 0.f;
    for (int j = t; j < (DP1 * BB) / 4; j += 256) {
        float4 v = Ue[j];
        a0 += v.x * v.x; a1 += v.y * v.y; a2 += v.z * v.z; a3 += v.w * v.w;
    }
    s[t * 4 + 0] = a0; s[t * 4 + 1] = a1; s[t * 4 + 2] = a2; s[t * 4 + 3] = a3;
    __syncthreads();
    if (t < BB) {
        int g = t >> 2, c = t & 3;
        float sum = 0.f;
        for (int i = g; i < 256; i += 4) sum += s[i * 4 + c];
        g_inv[e * BB + t] = rsqrtf(sum);
    }
}

// ---------------------------------------------------------------------------
// K2: deterministic per-expert compaction (counting sort into fixed slabs).
// ---------------------------------------------------------------------------
__global__ void __launch_bounds__(256) bucket_kernel(const int* __restrict__ topk) {
    __shared__ int s[256];
    const int e = blockIdx.x, t = threadIdx.x;
    int cnt = 0;
    for (int p = t; p < NPAIR; p += 256) cnt += (topk[p] == e);
    s[t] = cnt;
    __syncthreads();
    for (int off = 1; off < 256; off <<= 1) {
        int v = (t >= off) ? s[t - off] : 0;
        __syncthreads();
        s[t] += v;
        __syncthreads();
    }
    int pos = s[t] - cnt;
    if (t == 255) g_cnt[e] = s[255];
    for (int p = t; p < NPAIR; p += 256)
        if (topk[p] == e) g_list[e * SLAB + pos++] = p;
}

// ---------------------------------------------------------------------------
// K3: phase 1 — per-expert partial writes into fp16 (R10 shape, f32x2 math).
// Thread t holds U rows d=2t,2t+1 as 16 packed f32x2 (32 regs).
// ---------------------------------------------------------------------------
__global__ void __launch_bounds__(256, 4) phase1_kernel(
    const float* __restrict__ h, const float* __restrict__ U)
{
    const int e = blockIdx.x, tix = blockIdx.y, t = threadIdx.x;
    __shared__ float  inv_s[BB];
    __shared__ int    plist[BATCH];
    __shared__ float4 c4s[BATCH * 4];
    const int cnt = g_cnt[e];
    if (t < BB) inv_s[t] = g_inv[e * BB + t];

    // load U rows as packed u64 pairs
    uint64_t u2[2][8];
#pragma unroll
    for (int dd = 0; dd < 2; ++dd) {
        const ulonglong2* Ur = reinterpret_cast<const ulonglong2*>(
            U + (size_t)e * DP1 * BB + (size_t)(2 * t + dd) * BB);
#pragma unroll
        for (int i = 0; i < 4; ++i) {
            ulonglong2 v = Ur[i];
            u2[dd][2 * i] = v.x; u2[dd][2 * i + 1] = v.y;
        }
    }
    __syncthreads();

    const int nbatch = (cnt + BATCH - 1) / BATCH;
    for (int bi = tix; bi < nbatch; bi += NT1) {
        const int base = bi * BATCH;
        const int nv = min(BATCH, cnt - base);
        __syncthreads();
        if (t < BATCH) {
            int j = base + t;
            plist[t] = (j < cnt) ? g_list[e * SLAB + j] : -1;
        }
        __syncthreads();
        float* cs = reinterpret_cast<float*>(c4s);
#pragma unroll
        for (int q = t; q < BATCH * BB; q += 256) {
            int pp = q >> 4, b = q & 15;
            int pid = plist[pp];
            cs[q] = (pid >= 0) ? h[(size_t)pid * BB + b] * inv_s[b] : 0.f;
        }
        __syncthreads();
#pragma unroll 2
        for (int pp = 0; pp < nv; ++pp) {
            const int pid = plist[pp];
            const ulonglong2* c2 = reinterpret_cast<const ulonglong2*>(&c4s[pp * 4]);
            ulonglong2 ca = c2[0], cb = c2[1], cc = c2[2], cd = c2[3];
            uint64_t cp[8] = {ca.x, ca.y, cb.x, cb.y, cc.x, cc.y, cd.x, cd.y};
            float w[2];
#pragma unroll
            for (int dd = 0; dd < 2; ++dd) {
                uint64_t acc = 0ULL;
#pragma unroll
                for (int j = 0; j < 8; ++j) FMA2(acc, u2[dd][j], cp[j]);
                float lo, hi;
                UNPACK2(lo, hi, acc);
                w[dd] = lo + hi;
            }
            __half2 pk = __floats2half2_rn(w[0], w[1]);
            reinterpret_cast<unsigned*>(g_wph + (size_t)pid * DD)[t] =
                *reinterpret_cast<unsigned*>(&pk);
        }
    }
}

// ---------------------------------------------------------------------------
// K4: combine fp16 partials (fixed k order, deterministic) -> fp32 writes.
// ---------------------------------------------------------------------------
__global__ void __launch_bounds__(256) combine_kernel(float* __restrict__ out) {
    const int gid = blockIdx.x * 256 + threadIdx.x;
    if (gid >= TOK_N * (DD / 4)) return;
    const int n = gid >> 7, q = gid & 127;
    const uint2* wp = reinterpret_cast<const uint2*>(g_wph + (size_t)n * KK * DD);
    float4 r = make_float4(0.f, 0.f, 0.f, 0.f);
#pragma unroll
    for (int k = 0; k < KK; ++k) {
        uint2 v = wp[k * 128 + q];
        float2 a = __half22float2(*reinterpret_cast<__half2*>(&v.x));
        float2 b = __half22float2(*reinterpret_cast<__half2*>(&v.y));
        r.x += a.x; r.y += a.y; r.z += b.x; r.w += b.y;
    }
    reinterpret_cast<float4*>(out)[gid] = r;
}

// ---------------------------------------------------------------------------
// K5: phase 2 — recon + loss (R10 structure: PPW=4, NT2=8, butterfly+select).
// Inner accumulation in packed f32x2 (32 u64 accumulators = same 64 regs,
// half the FFMA issue count). U staged in stride-20 SMEM (conflict-free
// LDS.128 for d = lane + 32j).
// ---------------------------------------------------------------------------
__global__ void __launch_bounds__(256) phase2_kernel(
    const float* __restrict__ h, const float* __restrict__ U,
    const float* __restrict__ w)
{
    __shared__ float Us[DD * 20];
    __shared__ float inv_s[BB];
    __shared__ float wacc[8];
    const int e = blockIdx.x, tix = blockIdx.y, t = threadIdx.x;
    const int lane = t & 31, wid = t >> 5;
    const int cnt = g_cnt[e];
    if (t < BB) inv_s[t] = g_inv[e * BB + t];

    const float4* Ub = reinterpret_cast<const float4*>(U + (size_t)e * DP1 * BB);
#pragma unroll
    for (int pass = 0; pass < 2; ++pass) {
        int d = pass * 256 + t;
        float4* dst = reinterpret_cast<float4*>(Us + d * 20);
#pragma unroll
        for (int i = 0; i < 4; ++i) dst[i] = Ub[d * 4 + i];
    }
    __syncthreads();

    float acc = 0.f;
    const int ngroups = (cnt + PPW - 1) / PPW;
    for (int g = tix * 8 + wid; g < ngroups; g += NT2 * 8) {
        int pid[PPW];
        const float* wr[PPW];
#pragma unroll
        for (int p = 0; p < PPW; ++p) {
            int j = g * PPW + p;
            pid[p] = (j < cnt) ? g_list[e * SLAB + j] : -1;
            wr[p] = (pid[p] >= 0) ? (w + (size_t)(pid[p] >> 2) * DD) : w;
        }
        uint64_t racc[PPW][8];
#pragma unroll
        for (int p = 0; p < PPW; ++p)
#pragma unroll
            for (int i = 0; i < 8; ++i) racc[p][i] = 0ULL;

#pragma unroll
        for (int jj = 0; jj < 16; ++jj) {
            const int d = lane + 32 * jj;
            const ulonglong2* ur2 = reinterpret_cast<const ulonglong2*>(Us + d * 20);
            float wv[PPW];
#pragma unroll
            for (int p = 0; p < PPW; ++p)
                wv[p] = (pid[p] >= 0) ? __ldg(wr[p] + d) : 0.f;
            ulonglong2 A = ur2[0], B = ur2[1], C = ur2[2], D = ur2[3];
#pragma unroll
            for (int p = 0; p < PPW; ++p) {
                uint64_t wp2;
                PACK2(wp2, wv[p]);
                FMA2(racc[p][0], A.x, wp2); FMA2(racc[p][1], A.y, wp2);
                FMA2(racc[p][2], B.x, wp2); FMA2(racc[p][3], B.y, wp2);
                FMA2(racc[p][4], C.x, wp2); FMA2(racc[p][5], C.y, wp2);
                FMA2(racc[p][6], D.x, wp2); FMA2(racc[p][7], D.y, wp2);
            }
        }
        // unpack to float4 view for the proven butterfly+select epilogue
        float4 r[PPW][4];
#pragma unroll
        for (int p = 0; p < PPW; ++p)
#pragma unroll
            for (int i = 0; i < 4; ++i) {
                UNPACK2(r[p][i].x, r[p][i].y, racc[p][2 * i]);
                UNPACK2(r[p][i].z, r[p][i].w, racc[p][2 * i + 1]);
            }
#pragma unroll
        for (int m = 16; m >= 1; m >>= 1) {
#pragma unroll
            for (int p = 0; p < PPW; ++p) {
#pragma unroll
                for (int i = 0; i < 4; ++i) {
                    r[p][i].x += __shfl_xor_sync(0xffffffffu, r[p][i].x, m);
                    r[p][i].y += __shfl_xor_sync(0xffffffffu, r[p][i].y, m);
                    r[p][i].z += __shfl_xor_sync(0xffffffffu, r[p][i].z, m);
                    r[p][i].w += __shfl_xor_sync(0xffffffffu, r[p][i].w, m);
                }
            }
        }
#pragma unroll
        for (int p = 0; p < PPW; ++p) {
            float sel = r[p][0].x;
            sel = (lane == 1)  ? r[p][0].y : sel; sel = (lane == 2)  ? r[p][0].z : sel;
            sel = (lane == 3)  ? r[p][0].w : sel; sel = (lane == 4)  ? r[p][1].x : sel;
            sel = (lane == 5)  ? r[p][1].y : sel; sel = (lane == 6)  ? r[p][1].z : sel;
            sel = (lane == 7)  ? r[p][1].w : sel; sel = (lane == 8)  ? r[p][2].x : sel;
            sel = (lane == 9)  ? r[p][2].y : sel; sel = (lane == 10) ? r[p][2].z : sel;
            sel = (lane == 11) ? r[p][2].w : sel; sel = (lane == 12) ? r[p][3].x : sel;
            sel = (lane == 13) ? r[p][3].y : sel; sel = (lane == 14) ? r[p][3].z : sel;
            sel = (lane == 15) ? r[p][3].w : sel;
            float dsq = 0.f;
            if (lane < BB && pid[p] >= 0) {
                float rec = sel * inv_s[lane];
                float tgt = __ldg(h + (size_t)pid[p] * BB + lane);
                float df = rec - tgt;
                dsq = df * df;
            }
#pragma unroll
            for (int m = 8; m >= 1; m >>= 1) dsq += __shfl_xor_sync(0xffffffffu, dsq, m);
            if (lane == 0) acc += dsq;
        }
    }
    __syncthreads();
    if (lane == 0) wacc[wid] = acc;
    __syncthreads();
    if (t == 0) {
        float s = 0.f;
#pragma unroll
        for (int i = 0; i < 8; ++i) s += wacc[i];
        g_partial[e * NT2 + tix] = s;
    }
}

// ---------------------------------------------------------------------------
// K6: deterministic fixed-tree loss reduction.
// ---------------------------------------------------------------------------
__global__ void __launch_bounds__(256) loss_kernel(float* __restrict__ out_loss) {
    __shared__ float s[256];
    const int t = threadIdx.x;
    float a = 0.f;
    for (int i = t; i < MM * NT2; i += 256) a += g_partial[i];
    s[t] = a;
    __syncthreads();
#pragma unroll
    for (int off = 128; off > 0; off >>= 1) {
        if (t < off) s[t] += s[t + off];
        __syncthreads();
    }
    if (t == 0) *out_loss = s[0] * (1.0f / (float)(TOK_N * KK * BB));
}

__global__ void fill_tail(float* __restrict__ out, int start, int total) {
    int i = start + blockIdx.x * blockDim.x + threadIdx.x;
    if (i < total) out[i] = 0.f;
}

extern "C" void kernel_launch(void* const* d_in, const int* in_sizes, int n_in,
                              void* d_out, int out_size) {
    const float* h_sparse = (const float*)d_in[0];
    const int*   topk     = (const int*)d_in[1];
    const float* U        = (const float*)d_in[2];
    float* out = (float*)d_out;

    norm_kernel<<<MM, 256>>>(U);
    bucket_kernel<<<MM, 256>>>(topk);
    phase1_kernel<<<dim3(MM, NT1), 256>>>(h_sparse, U);
    combine_kernel<<<(TOK_N * (DD / 4) + 255) / 256, 256>>>(out);
    phase2_kernel<<<dim3(MM, NT2), 256>>>(h_sparse, U, out);
    loss_kernel<<<1, 256>>>(out + (size_t)TOK_N * DD);

    int tail_start = TOK_N * DD + 1;
    if (out_size > tail_start) {
        int tail = out_size - tail_start;
        fill_tail<<<(tail + 255) / 256, 256>>>(out, tail_start, out_size);
    }
}

// round 16
// speedup vs baseline: 1.8831x; 1.8831x over previous
#include <cuda_runtime.h>
#include <cuda_fp16.h>
#include <cstddef>

#define TOK_N 8192
#define KK    4
#define BB    16
#define MM    64
#define DD    512
#define DP1   513
#define NPAIR (TOK_N*KK)   // 32768
#define SLAB  1024
#define NT1   9            // phase1 tiles per expert
#define BATCH 32           // pairs per phase1 batch
#define NT2   8            // phase2 tiles per expert
#define PPW   4            // phase2 pairs per warp per sweep

// ---- scratch ----
__device__ float  g_inv[MM * BB];
__device__ int    g_cnt[MM];
__device__ int    g_list[MM * SLAB];
__device__ __half g_wph[(size_t)NPAIR * DD];   // 32 MB fp16 partials
__device__ float  g_partial[MM * NT2];

// ---------------------------------------------------------------------------
// K1: fused norm + bucket (independent halves; saves one launch tail).
// ---------------------------------------------------------------------------
__global__ void __launch_bounds__(256) prep_kernel(
    const float* __restrict__ U, const int* __restrict__ topk)
{
    __shared__ float sf[256 * 4];
    const int t = threadIdx.x;
    if (blockIdx.x < MM) {
        const int e = blockIdx.x;
        const float4* Ue = reinterpret_cast<const float4*>(U + (size_t)e * DP1 * BB);
        float a0 = 0.f, a1 = 0.f, a2 = 0.f, a3 = 0.f;
        for (int j = t; j < (DP1 * BB) / 4; j += 256) {
            float4 v = Ue[j];
            a0 += v.x * v.x; a1 += v.y * v.y; a2 += v.z * v.z; a3 += v.w * v.w;
        }
        sf[t * 4 + 0] = a0; sf[t * 4 + 1] = a1; sf[t * 4 + 2] = a2; sf[t * 4 + 3] = a3;
        __syncthreads();
        if (t < BB) {
            int g = t >> 2, c = t & 3;
            float sum = 0.f;
            for (int i = g; i < 256; i += 4) sum += sf[i * 4 + c];
            g_inv[e * BB + t] = rsqrtf(sum);
        }
    } else {
        int* s = reinterpret_cast<int*>(sf);
        const int e = blockIdx.x - MM;
        int cnt = 0;
        for (int p = t; p < NPAIR; p += 256) cnt += (topk[p] == e);
        s[t] = cnt;
        __syncthreads();
        for (int off = 1; off < 256; off <<= 1) {
            int v = (t >= off) ? s[t - off] : 0;
            __syncthreads();
            s[t] += v;
            __syncthreads();
        }
        int pos = s[t] - cnt;
        if (t == 255) g_cnt[e] = s[255];
        for (int p = t; p < NPAIR; p += 256)
            if (topk[p] == e) g_list[e * SLAB + pos++] = p;
    }
}

// ---------------------------------------------------------------------------
// K2: phase 1 — per-expert partial writes into fp16 (R10-proven, verbatim).
// Thread t holds U rows d=2t,2t+1 (32 regs); per pair 32 FFMA vs smem
// coeffs, then one packed STG.32 (half2).
// ---------------------------------------------------------------------------
__global__ void __launch_bounds__(256, 4) phase1_kernel(
    const float* __restrict__ h, const float* __restrict__ U)
{
    const int e = blockIdx.x, tix = blockIdx.y, t = threadIdx.x;
    __shared__ float  inv_s[BB];
    __shared__ int    plist[BATCH];
    __shared__ float4 c4s[BATCH * 4];
    const int cnt = g_cnt[e];
    if (t < BB) inv_s[t] = g_inv[e * BB + t];

    const float4* Ub = reinterpret_cast<const float4*>(U + (size_t)e * DP1 * BB);
    float4 u[2][4];
#pragma unroll
    for (int dd = 0; dd < 2; ++dd)
#pragma unroll
        for (int i = 0; i < 4; ++i)
            u[dd][i] = Ub[(2 * t + dd) * 4 + i];
    __syncthreads();

    const int nbatch = (cnt + BATCH - 1) / BATCH;
    for (int bi = tix; bi < nbatch; bi += NT1) {
        const int base = bi * BATCH;
        const int nv = min(BATCH, cnt - base);
        __syncthreads();
        if (t < BATCH) {
            int j = base + t;
            plist[t] = (j < cnt) ? g_list[e * SLAB + j] : -1;
        }
        __syncthreads();
        float* cs = reinterpret_cast<float*>(c4s);
#pragma unroll
        for (int q = t; q < BATCH * BB; q += 256) {
            int pp = q >> 4, b = q & 15;
            int pid = plist[pp];
            cs[q] = (pid >= 0) ? h[(size_t)pid * BB + b] * inv_s[b] : 0.f;
        }
        __syncthreads();
#pragma unroll 2
        for (int pp = 0; pp < nv; ++pp) {
            const int pid = plist[pp];
            const float4 c0 = c4s[pp * 4 + 0], c1 = c4s[pp * 4 + 1];
            const float4 c2 = c4s[pp * 4 + 2], c3 = c4s[pp * 4 + 3];
            float w[2];
#pragma unroll
            for (int dd = 0; dd < 2; ++dd) {
                float a;
                a  = u[dd][0].x * c0.x + u[dd][0].y * c0.y + u[dd][0].z * c0.z + u[dd][0].w * c0.w;
                a += u[dd][1].x * c1.x + u[dd][1].y * c1.y + u[dd][1].z * c1.z + u[dd][1].w * c1.w;
                a += u[dd][2].x * c2.x + u[dd][2].y * c2.y + u[dd][2].z * c2.z + u[dd][2].w * c2.w;
                a += u[dd][3].x * c3.x + u[dd][3].y * c3.y + u[dd][3].z * c3.z + u[dd][3].w * c3.w;
                w[dd] = a;
            }
            __half2 pk = __floats2half2_rn(w[0], w[1]);
            reinterpret_cast<unsigned*>(g_wph + (size_t)pid * DD)[t] =
                *reinterpret_cast<unsigned*>(&pk);
        }
    }
}

// ---------------------------------------------------------------------------
// K3: combine fp16 partials (fixed k order, deterministic) -> fp32 writes.
// ---------------------------------------------------------------------------
__global__ void __launch_bounds__(256) combine_kernel(float* __restrict__ out) {
    const int gid = blockIdx.x * 256 + threadIdx.x;
    if (gid >= TOK_N * (DD / 4)) return;
    const int n = gid >> 7, q = gid & 127;
    const uint2* wp = reinterpret_cast<const uint2*>(g_wph + (size_t)n * KK * DD);
    float4 r = make_float4(0.f, 0.f, 0.f, 0.f);
#pragma unroll
    for (int k = 0; k < KK; ++k) {
        uint2 v = wp[k * 128 + q];
        float2 a = __half22float2(*reinterpret_cast<__half2*>(&v.x));
        float2 b = __half22float2(*reinterpret_cast<__half2*>(&v.y));
        r.x += a.x; r.y += a.y; r.z += b.x; r.w += b.y;
    }
    reinterpret_cast<float4*>(out)[gid] = r;
}

// ---------------------------------------------------------------------------
// K4: phase 2 — recon + loss (R10-proven, verbatim). U staged once per block
// in stride-20 SMEM (conflict-free LDS.128 for d = lane + 32j). Each warp
// processes PPW=4 pairs per sweep. Butterfly-reduce + 16-way select.
// ---------------------------------------------------------------------------
__global__ void __launch_bounds__(256) phase2_kernel(
    const float* __restrict__ h, const float* __restrict__ U,
    const float* __restrict__ w)
{
    __shared__ float Us[DD * 20];
    __shared__ float inv_s[BB];
    __shared__ float wacc[8];
    const int e = blockIdx.x, tix = blockIdx.y, t = threadIdx.x;
    const int lane = t & 31, wid = t >> 5;
    const int cnt = g_cnt[e];
    if (t < BB) inv_s[t] = g_inv[e * BB + t];

    const float4* Ub = reinterpret_cast<const float4*>(U + (size_t)e * DP1 * BB);
#pragma unroll
    for (int pass = 0; pass < 2; ++pass) {
        int d = pass * 256 + t;
        float4* dst = reinterpret_cast<float4*>(Us + d * 20);
#pragma unroll
        for (int i = 0; i < 4; ++i) dst[i] = Ub[d * 4 + i];
    }
    __syncthreads();

    float acc = 0.f;
    const int ngroups = (cnt + PPW - 1) / PPW;
    for (int g = tix * 8 + wid; g < ngroups; g += NT2 * 8) {
        int pid[PPW];
        const float* wr[PPW];
#pragma unroll
        for (int p = 0; p < PPW; ++p) {
            int j = g * PPW + p;
            pid[p] = (j < cnt) ? g_list[e * SLAB + j] : -1;
            wr[p] = (pid[p] >= 0) ? (w + (size_t)(pid[p] >> 2) * DD) : w;
        }
        float4 r[PPW][4];
#pragma unroll
        for (int p = 0; p < PPW; ++p)
#pragma unroll
            for (int i = 0; i < 4; ++i) r[p][i] = make_float4(0, 0, 0, 0);

#pragma unroll
        for (int jj = 0; jj < 16; ++jj) {
            const int d = lane + 32 * jj;
            const float4* ur = reinterpret_cast<const float4*>(Us + d * 20);
            float wv[PPW];
#pragma unroll
            for (int p = 0; p < PPW; ++p)
                wv[p] = (pid[p] >= 0) ? __ldg(wr[p] + d) : 0.f;
            float4 u0 = ur[0], u1 = ur[1], u2 = ur[2], u3 = ur[3];
#pragma unroll
            for (int p = 0; p < PPW; ++p) {
                r[p][0].x += u0.x * wv[p]; r[p][0].y += u0.y * wv[p];
                r[p][0].z += u0.z * wv[p]; r[p][0].w += u0.w * wv[p];
                r[p][1].x += u1.x * wv[p]; r[p][1].y += u1.y * wv[p];
                r[p][1].z += u1.z * wv[p]; r[p][1].w += u1.w * wv[p];
                r[p][2].x += u2.x * wv[p]; r[p][2].y += u2.y * wv[p];
                r[p][2].z += u2.z * wv[p]; r[p][2].w += u2.w * wv[p];
                r[p][3].x += u3.x * wv[p]; r[p][3].y += u3.y * wv[p];
                r[p][3].z += u3.z * wv[p]; r[p][3].w += u3.w * wv[p];
            }
        }
#pragma unroll
        for (int m = 16; m >= 1; m >>= 1) {
#pragma unroll
            for (int p = 0; p < PPW; ++p) {
#pragma unroll
                for (int i = 0; i < 4; ++i) {
                    r[p][i].x += __shfl_xor_sync(0xffffffffu, r[p][i].x, m);
                    r[p][i].y += __shfl_xor_sync(0xffffffffu, r[p][i].y, m);
                    r[p][i].z += __shfl_xor_sync(0xffffffffu, r[p][i].z, m);
                    r[p][i].w += __shfl_xor_sync(0xffffffffu, r[p][i].w, m);
                }
            }
        }
#pragma unroll
        for (int p = 0; p < PPW; ++p) {
            float sel = r[p][0].x;
            sel = (lane == 1)  ? r[p][0].y : sel; sel = (lane == 2)  ? r[p][0].z : sel;
            sel = (lane == 3)  ? r[p][0].w : sel; sel = (lane == 4)  ? r[p][1].x : sel;
            sel = (lane == 5)  ? r[p][1].y : sel; sel = (lane == 6)  ? r[p][1].z : sel;
            sel = (lane == 7)  ? r[p][1].w : sel; sel = (lane == 8)  ? r[p][2].x : sel;
            sel = (lane == 9)  ? r[p][2].y : sel; sel = (lane == 10) ? r[p][2].z : sel;
            sel = (lane == 11) ? r[p][2].w : sel; sel = (lane == 12) ? r[p][3].x : sel;
            sel = (lane == 13) ? r[p][3].y : sel; sel = (lane == 14) ? r[p][3].z : sel;
            sel = (lane == 15) ? r[p][3].w : sel;
            float dsq = 0.f;
            if (lane < BB && pid[p] >= 0) {
                float rec = sel * inv_s[lane];
                float tgt = __ldg(h + (size_t)pid[p] * BB + lane);
                float df = rec - tgt;
                dsq = df * df;
            }
#pragma unroll
            for (int m = 8; m >= 1; m >>= 1) dsq += __shfl_xor_sync(0xffffffffu, dsq, m);
            if (lane == 0) acc += dsq;
        }
    }
    __syncthreads();
    if (lane == 0) wacc[wid] = acc;
    __syncthreads();
    if (t == 0) {
        float s = 0.f;
#pragma unroll
        for (int i = 0; i < 8; ++i) s += wacc[i];
        g_partial[e * NT2 + tix] = s;
    }
}

// ---------------------------------------------------------------------------
// K5: deterministic fixed-tree loss reduction.
// ---------------------------------------------------------------------------
__global__ void __launch_bounds__(256) loss_kernel(float* __restrict__ out_loss) {
    __shared__ float s[256];
    const int t = threadIdx.x;
    float a = 0.f;
    for (int i = t; i < MM * NT2; i += 256) a += g_partial[i];
    s[t] = a;
    __syncthreads();
#pragma unroll
    for (int off = 128; off > 0; off >>= 1) {
        if (t < off) s[t] += s[t + off];
        __syncthreads();
    }
    if (t == 0) *out_loss = s[0] * (1.0f / (float)(TOK_N * KK * BB));
}

__global__ void fill_tail(float* __restrict__ out, int start, int total) {
    int i = start + blockIdx.x * blockDim.x + threadIdx.x;
    if (i < total) out[i] = 0.f;
}

extern "C" void kernel_launch(void* const* d_in, const int* in_sizes, int n_in,
                              void* d_out, int out_size) {
    const float* h_sparse = (const float*)d_in[0];
    const int*   topk     = (const int*)d_in[1];
    const float* U        = (const float*)d_in[2];
    float* out = (float*)d_out;

    prep_kernel<<<2 * MM, 256>>>(U, topk);
    phase1_kernel<<<dim3(MM, NT1), 256>>>(h_sparse, U);
    combine_kernel<<<(TOK_N * (DD / 4) + 255) / 256, 256>>>(out);
    phase2_kernel<<<dim3(MM, NT2), 256>>>(h_sparse, U, out);
    loss_kernel<<<1, 256>>>(out + (size_t)TOK_N * DD);

    int tail_start = TOK_N * DD + 1;
    if (out_size > tail_start) {
        int tail = out_size - tail_start;
        fill_tail<<<(tail + 255) / 256, 256>>>(out, tail_start, out_size);
    }
}